// round 2
// baseline (speedup 1.0000x reference)
#include <cuda_runtime.h>
#include <cuda_bf16.h>

#define INPUT_SIZE 1024
#define HIDDEN     1024
#define BATCH      32
#define LLEN       2048
#define BL         (BATCH * LLEN)   // 65536
#define NCOLTILES  16               // HIDDEN / 64

// Scratch (static device globals — no allocations allowed)
__device__ float g_bias[HIDDEN];                 // ln_b + W_vq @ vq
__device__ float g_spart[NCOLTILES * BL];        // per-column-tile partial s  (4 MB)
__device__ float g_a[BL];                        // softmax weights

// ---------------------------------------------------------------------------
// Kernel 1: bias[hh] = ln_b[hh] + sum_i ln_w[hh, 1024+i] * vq[i]
// ---------------------------------------------------------------------------
__global__ void bias_kernel(const float* __restrict__ ln_w,
                            const float* __restrict__ ln_b,
                            const float* __restrict__ vq) {
    int hh = blockIdx.x;
    const float* wrow = ln_w + (size_t)hh * 2048 + 1024;
    float sum = 0.f;
    for (int i = threadIdx.x; i < 1024; i += 256)
        sum = fmaf(wrow[i], vq[i], sum);
    __shared__ float red[256];
    red[threadIdx.x] = sum;
    __syncthreads();
    for (int st = 128; st > 0; st >>= 1) {
        if (threadIdx.x < st) red[threadIdx.x] += red[threadIdx.x + st];
        __syncthreads();
    }
    if (threadIdx.x == 0) g_bias[hh] = ln_b[hh] + red[0];
}

// ---------------------------------------------------------------------------
// Kernel 2: fused GEMM + tanh + dot(v_w) -> partial s per column tile.
//   pre[r, c] = sum_k h[r, k] * ln_w[c, k]   (r = b*L + l, c = hidden idx)
//   g_spart[ct*BL + r] = sum_{c in tile} tanh(pre + bias[c]) * v_w[c]
// Tiling: BM=64 rows, BN=64 cols, BK=16, 256 threads, 4x4 per thread.
// Deterministic: each column tile writes its own partial array (no atomics).
// ---------------------------------------------------------------------------
__global__ void __launch_bounds__(256)
gemm_s_kernel(const float* __restrict__ h,
              const float* __restrict__ ln_w,
              const float* __restrict__ v_w) {
    __shared__ __align__(16) float As[16][68];   // [k][row], padded
    __shared__ __align__(16) float Bs[16][68];   // [k][col], padded

    const int tid  = threadIdx.x;
    const int tx   = tid & 15;          // 0..15 -> column group
    const int ty   = tid >> 4;          // 0..15 -> row group
    const int row0 = blockIdx.y * 64;
    const int col0 = blockIdx.x * 64;

    // Per-thread global-load coordinates: one float4 from A, one from B per k-tile
    const int lr = tid >> 2;            // 0..63  tile row
    const int lk = (tid & 3) * 4;       // 0,4,8,12 k offset
    const float* Aptr = h    + (size_t)(row0 + lr) * 1024 + lk;
    const float* Bptr = ln_w + (size_t)(col0 + lr) * 2048 + lk;   // W_h = first 1024 cols

    float acc[4][4] = {};

    for (int kt = 0; kt < 1024; kt += 16) {
        float4 av = *reinterpret_cast<const float4*>(Aptr + kt);
        float4 bv = *reinterpret_cast<const float4*>(Bptr + kt);
        As[lk + 0][lr] = av.x; As[lk + 1][lr] = av.y;
        As[lk + 2][lr] = av.z; As[lk + 3][lr] = av.w;
        Bs[lk + 0][lr] = bv.x; Bs[lk + 1][lr] = bv.y;
        Bs[lk + 2][lr] = bv.z; Bs[lk + 3][lr] = bv.w;
        __syncthreads();

        #pragma unroll
        for (int k = 0; k < 16; k++) {
            float4 af = *reinterpret_cast<const float4*>(&As[k][ty * 4]);
            float4 bf = *reinterpret_cast<const float4*>(&Bs[k][tx * 4]);
            float a[4] = {af.x, af.y, af.z, af.w};
            float b[4] = {bf.x, bf.y, bf.z, bf.w};
            #pragma unroll
            for (int i = 0; i < 4; i++)
                #pragma unroll
                for (int j = 0; j < 4; j++)
                    acc[i][j] = fmaf(a[i], b[j], acc[i][j]);
        }
        __syncthreads();
    }

    // Epilogue: tanh, dot with v_w over this thread's 4 columns
    float sp[4];
    #pragma unroll
    for (int i = 0; i < 4; i++) {
        float sum = 0.f;
        #pragma unroll
        for (int j = 0; j < 4; j++) {
            int c = col0 + tx * 4 + j;
            float p = tanhf(acc[i][j] + g_bias[c]);
            sum = fmaf(p, v_w[c], sum);
        }
        sp[i] = sum;
    }
    // Reduce across the 16 tx lanes (lanes 0-15 / 16-31 are independent halves)
    #pragma unroll
    for (int off = 8; off > 0; off >>= 1) {
        #pragma unroll
        for (int i = 0; i < 4; i++)
            sp[i] += __shfl_down_sync(0xffffffffu, sp[i], off, 16);
    }
    if (tx == 0) {
        float* dst = g_spart + (size_t)blockIdx.x * BL + row0 + ty * 4;
        #pragma unroll
        for (int i = 0; i < 4; i++) dst[i] = sp[i];
    }
}

// ---------------------------------------------------------------------------
// Kernel 3: per-batch softmax over L with mask (int32: bool promoted by
// harness); sums the 16 column-tile partials first. Writes weights to g_a.
// ---------------------------------------------------------------------------
__global__ void softmax_kernel(const int* __restrict__ mask) {
    int b = blockIdx.x;
    __shared__ float red[256];
    float vals[8];
    float mx = -1e30f;
    #pragma unroll
    for (int j = 0; j < 8; j++) {
        int l = threadIdx.x + j * 256;
        int idx = b * LLEN + l;
        float v = 0.f;
        #pragma unroll
        for (int ct = 0; ct < NCOLTILES; ct++)
            v += g_spart[(size_t)ct * BL + idx];
        if (mask[idx] == 0) v -= 10000.f;
        vals[j] = v;
        mx = fmaxf(mx, v);
    }
    red[threadIdx.x] = mx;
    __syncthreads();
    for (int st = 128; st > 0; st >>= 1) {
        if (threadIdx.x < st) red[threadIdx.x] = fmaxf(red[threadIdx.x], red[threadIdx.x + st]);
        __syncthreads();
    }
    mx = red[0];
    __syncthreads();

    float se = 0.f;
    #pragma unroll
    for (int j = 0; j < 8; j++) {
        vals[j] = __expf(vals[j] - mx);
        se += vals[j];
    }
    red[threadIdx.x] = se;
    __syncthreads();
    for (int st = 128; st > 0; st >>= 1) {
        if (threadIdx.x < st) red[threadIdx.x] += red[threadIdx.x + st];
        __syncthreads();
    }
    float inv = 1.f / red[0];
    #pragma unroll
    for (int j = 0; j < 8; j++)
        g_a[b * LLEN + threadIdx.x + j * 256] = vals[j] * inv;
}

// ---------------------------------------------------------------------------
// Kernel 4: r[b, c] = sum_l a[b,l] * h[b,l,c]. Deterministic (no atomics):
// each block owns one (batch, 256-column chunk) and walks all L.
// grid = (4, 32), 256 threads.
// ---------------------------------------------------------------------------
__global__ void __launch_bounds__(256)
wsum_kernel(const float* __restrict__ h, float* __restrict__ out) {
    int b = blockIdx.y;
    int c = blockIdx.x * 256 + threadIdx.x;
    __shared__ float aw[LLEN];
    for (int l = threadIdx.x; l < LLEN; l += 256)
        aw[l] = g_a[b * LLEN + l];
    __syncthreads();

    const float* hp = h + (size_t)b * LLEN * 1024 + c;
    float acc = 0.f;
    #pragma unroll 8
    for (int l = 0; l < LLEN; l++)
        acc = fmaf(aw[l], hp[(size_t)l * 1024], acc);
    out[b * 1024 + c] = acc;
}

// ---------------------------------------------------------------------------
extern "C" void kernel_launch(void* const* d_in, const int* in_sizes, int n_in,
                              void* d_out, int out_size) {
    const float* h    = (const float*)d_in[0];
    const int*   mask = (const int*)d_in[1];     // bool promoted to int32 by harness
    const float* ln_w = (const float*)d_in[2];
    const float* ln_b = (const float*)d_in[3];
    const float* v_w  = (const float*)d_in[4];
    const float* vq   = (const float*)d_in[5];
    float* out = (float*)d_out;

    bias_kernel<<<HIDDEN, 256>>>(ln_w, ln_b, vq);

    dim3 ggrid(NCOLTILES, BL / 64);           // (16, 1024)
    gemm_s_kernel<<<ggrid, 256>>>(h, ln_w, v_w);

    softmax_kernel<<<BATCH, 256>>>(mask);

    dim3 wgrid(4, BATCH);                     // (4, 32)
    wsum_kernel<<<wgrid, 256>>>(h, out);
}

// round 4
// speedup vs baseline: 3.0477x; 3.0477x over previous
#include <cuda_runtime.h>
#include <cuda_bf16.h>
#include <cstdint>

#define BATCH 32
#define LLEN  2048
#define BL    (BATCH * LLEN)      // 65536
#define NCTS  16                  // 16 partial s arrays (8 ntiles x 2 warp halves)

// ------------------------------- device scratch ----------------------------
__device__ __align__(16) __nv_bfloat16 g_h_hi[67108864];   // [BL][1024]
__device__ __align__(16) __nv_bfloat16 g_h_lo[67108864];
__device__ __align__(16) __nv_bfloat16 g_w_hi[1048576];    // [1024 N][1024 K]
__device__ __align__(16) __nv_bfloat16 g_w_lo[1048576];
__device__ float g_bias[1024];
__device__ float g_spart[NCTS * BL];
__device__ float g_a[BL];
__device__ float g_rpart[8][BATCH * 1024];

// ------------------------------- PTX helpers -------------------------------
__device__ __forceinline__ uint32_t smem_u32(const void* p) {
    uint32_t a;
    asm("{ .reg .u64 t; cvta.to.shared.u64 t, %1; cvt.u32.u64 %0, t; }" : "=r"(a) : "l"(p));
    return a;
}
__device__ __forceinline__ void cp16(uint32_t dst, const void* src) {
    asm volatile("cp.async.cg.shared.global [%0], [%1], 16;" :: "r"(dst), "l"(src));
}
#define LDSM4(r, addr) \
    asm volatile("ldmatrix.sync.aligned.m8n8.x4.shared.b16 {%0,%1,%2,%3}, [%4];" \
        : "=r"((r)[0]), "=r"((r)[1]), "=r"((r)[2]), "=r"((r)[3]) : "r"(addr))

__device__ __forceinline__ void mma16816(float* d, const uint32_t* a,
                                         uint32_t b0, uint32_t b1) {
    asm volatile("mma.sync.aligned.m16n8k16.row.col.f32.bf16.bf16.f32 "
        "{%0,%1,%2,%3}, {%4,%5,%6,%7}, {%8,%9}, {%0,%1,%2,%3};"
        : "+f"(d[0]), "+f"(d[1]), "+f"(d[2]), "+f"(d[3])
        : "r"(a[0]), "r"(a[1]), "r"(a[2]), "r"(a[3]), "r"(b0), "r"(b1));
}

__device__ __forceinline__ float tanh_fast(float x) {
    float e = __expf(2.f * x);
    return 1.f - 2.f / (e + 1.f);
}

// ------------------------------- GEMM constants ----------------------------
// Per stage (64 KB): A_hi 16K | A_lo 16K | B_hi 16K | B_lo 16K (128 rows x 128B, SW128)
#define STAGE_STRIDE 65536
#define OFF_A_HI 0
#define OFF_A_LO 16384
#define OFF_B_HI 32768
#define OFF_B_LO 49152
#define OFF_SBIAS 131072
#define OFF_SVW   131584
#define SMEM_BYTES 132096

// Issue cp.asyncs for one K-chunk (64 bf16 wide) into stage `buf`.
// 256 threads: seg = tid&7 (16B), r0 = tid>>3 (0..31), rows r0 + v*32.
__device__ __forceinline__ void issue_chunk(uint32_t sb, int buf, int kc,
                                            int m0, int n0, int tid) {
    const int seg = tid & 7;
    const int r0  = tid >> 3;
    const size_t gbase = (size_t)kc * 64 + seg * 8;
    uint32_t sbase = sb + buf * STAGE_STRIDE;
#pragma unroll
    for (int v = 0; v < 4; v++) {
        int r = r0 + v * 32;
        uint32_t soff = (uint32_t)r * 128 + (uint32_t)((seg ^ (r & 7)) * 16);
        const size_t gA = (size_t)(m0 + r) * 1024 + gbase;
        const size_t gB = (size_t)(n0 + r) * 1024 + gbase;
        cp16(sbase + OFF_A_HI + soff, g_h_hi + gA);
        cp16(sbase + OFF_A_LO + soff, g_h_lo + gA);
        cp16(sbase + OFF_B_HI + soff, g_w_hi + gB);
        cp16(sbase + OFF_B_LO + soff, g_w_lo + gB);
    }
    asm volatile("cp.async.commit_group;" ::: "memory");
}

// ---------------------------------------------------------------------------
// HMMA GEMM: pre[128 rows, 128 cols] over K=1024, 3-term bf16 split fused in
// one k-loop; epilogue tanh(pre+bias)@v_w -> g_spart (per 64-col half).
// grid (8 ntiles, 512 mtiles), 256 threads (8 warps: 4 M x 2 N).
// ---------------------------------------------------------------------------
__global__ void __launch_bounds__(256, 1)
gemm_mma_kernel(const float* __restrict__ v_w) {
    extern __shared__ char smem[];
    const uint32_t sb = smem_u32(smem);
    const int tid  = threadIdx.x;
    const int lane = tid & 31;
    const int warp = tid >> 5;
    const int wm   = warp & 3;        // 0..3: 32-row slice
    const int wn   = warp >> 2;       // 0..1: 64-col slice
    const int m0 = blockIdx.y * 128;
    const int n0 = blockIdx.x * 128;

    float* sbias = (float*)(smem + OFF_SBIAS);
    float* svw   = (float*)(smem + OFF_SVW);
    if (tid < 128) {
        sbias[tid] = g_bias[n0 + tid];
        svw[tid]   = v_w[n0 + tid];
    }

    float acc[2][8][4] = {};

    const int lrow  = lane & 15;
    const int lhalf = lane >> 4;

    issue_chunk(sb, 0, 0, m0, n0, tid);
    issue_chunk(sb, 1, 1, m0, n0, tid);

    for (int c = 0; c < 16; c++) {
        const int buf = c & 1;
        asm volatile("cp.async.wait_group %0;" :: "n"(1));
        __syncthreads();
        const uint32_t st = sb + buf * STAGE_STRIDE;

#pragma unroll
        for (int ks = 0; ks < 4; ks++) {
            // A fragments (2 m-steps, hi+lo)
            uint32_t a_hi[2][4], a_lo[2][4];
#pragma unroll
            for (int mi = 0; mi < 2; mi++) {
                int r = wm * 32 + mi * 16 + lrow;
                uint32_t boff = (uint32_t)(((ks * 2 + lhalf) ^ (r & 7)) * 16);
                uint32_t off = (uint32_t)r * 128 + boff;
                LDSM4(a_hi[mi], st + OFF_A_HI + off);
                LDSM4(a_lo[mi], st + OFF_A_LO + off);
            }
            // B fragments (4 groups of 16 n, hi+lo)
            uint32_t b_hi[4][4], b_lo[4][4];
#pragma unroll
            for (int ng = 0; ng < 4; ng++) {
                int r = wn * 64 + ng * 16 + lrow;
                uint32_t boff = (uint32_t)(((ks * 2 + lhalf) ^ (r & 7)) * 16);
                uint32_t off = (uint32_t)r * 128 + boff;
                LDSM4(b_hi[ng], st + OFF_B_HI + off);
                LDSM4(b_lo[ng], st + OFF_B_LO + off);
            }
#pragma unroll
            for (int mi = 0; mi < 2; mi++)
#pragma unroll
                for (int nt = 0; nt < 8; nt++) {
                    int ng = nt >> 1, hf = nt & 1;
                    mma16816(acc[mi][nt], a_hi[mi], b_hi[ng][hf], b_hi[ng][2 + hf]);
                    mma16816(acc[mi][nt], a_hi[mi], b_lo[ng][hf], b_lo[ng][2 + hf]);
                    mma16816(acc[mi][nt], a_lo[mi], b_hi[ng][hf], b_hi[ng][2 + hf]);
                }
        }
        __syncthreads();
        if (c < 14) issue_chunk(sb, buf, c + 2, m0, n0, tid);
    }

    // Epilogue: tanh(acc + bias) dot v_w, reduced over this warp's 64 cols.
    const int g = lane >> 2, tig = lane & 3;
#pragma unroll
    for (int mi = 0; mi < 2; mi++)
#pragma unroll
        for (int rg = 0; rg < 2; rg++) {
            float s = 0.f;
#pragma unroll
            for (int nt = 0; nt < 8; nt++) {
                int col = wn * 64 + nt * 8 + tig * 2;
                float p0 = acc[mi][nt][rg * 2 + 0] + sbias[col];
                float p1 = acc[mi][nt][rg * 2 + 1] + sbias[col + 1];
                s = fmaf(tanh_fast(p0), svw[col], s);
                s = fmaf(tanh_fast(p1), svw[col + 1], s);
            }
            s += __shfl_down_sync(0xffffffffu, s, 1, 4);
            s += __shfl_down_sync(0xffffffffu, s, 2, 4);
            if (tig == 0) {
                int row = m0 + wm * 32 + mi * 16 + rg * 8 + g;
                g_spart[(size_t)(blockIdx.x * 2 + wn) * BL + row] = s;
            }
        }
}

// ------------------------------- small kernels -----------------------------
__global__ void convert_h_kernel(const float* __restrict__ h) {
    size_t i = ((size_t)blockIdx.x * 256 + threadIdx.x) * 4;
    float4 v = *reinterpret_cast<const float4*>(h + i);
    union { __nv_bfloat16 b[4]; uint64_t u; } Hi, Lo;
    float xs[4] = {v.x, v.y, v.z, v.w};
#pragma unroll
    for (int j = 0; j < 4; j++) {
        __nv_bfloat16 hb = __float2bfloat16_rn(xs[j]);
        Hi.b[j] = hb;
        Lo.b[j] = __float2bfloat16_rn(xs[j] - __bfloat162float(hb));
    }
    *reinterpret_cast<uint64_t*>(g_h_hi + i) = Hi.u;
    *reinterpret_cast<uint64_t*>(g_h_lo + i) = Lo.u;
}

__global__ void convert_w_kernel(const float* __restrict__ ln_w) {
    size_t e = ((size_t)blockIdx.x * 256 + threadIdx.x) * 4;
    int n = (int)(e >> 10), k = (int)(e & 1023);
    float4 v = *reinterpret_cast<const float4*>(ln_w + (size_t)n * 2048 + k);
    union { __nv_bfloat16 b[4]; uint64_t u; } Hi, Lo;
    float xs[4] = {v.x, v.y, v.z, v.w};
#pragma unroll
    for (int j = 0; j < 4; j++) {
        __nv_bfloat16 hb = __float2bfloat16_rn(xs[j]);
        Hi.b[j] = hb;
        Lo.b[j] = __float2bfloat16_rn(xs[j] - __bfloat162float(hb));
    }
    *reinterpret_cast<uint64_t*>(g_w_hi + e) = Hi.u;
    *reinterpret_cast<uint64_t*>(g_w_lo + e) = Lo.u;
}

__global__ void bias_kernel(const float* __restrict__ ln_w,
                            const float* __restrict__ ln_b,
                            const float* __restrict__ vq) {
    int hh = blockIdx.x;
    const float* wrow = ln_w + (size_t)hh * 2048 + 1024;
    float sum = 0.f;
    for (int i = threadIdx.x; i < 1024; i += 256)
        sum = fmaf(wrow[i], vq[i], sum);
    __shared__ float red[256];
    red[threadIdx.x] = sum;
    __syncthreads();
    for (int st = 128; st > 0; st >>= 1) {
        if (threadIdx.x < st) red[threadIdx.x] += red[threadIdx.x + st];
        __syncthreads();
    }
    if (threadIdx.x == 0) g_bias[hh] = ln_b[hh] + red[0];
}

__global__ void softmax_kernel(const int* __restrict__ mask) {
    int b = blockIdx.x;
    __shared__ float red[256];
    float vals[8];
    float mx = -1e30f;
#pragma unroll
    for (int j = 0; j < 8; j++) {
        int idx = b * LLEN + threadIdx.x + j * 256;
        float v = 0.f;
#pragma unroll
        for (int ct = 0; ct < NCTS; ct++)
            v += g_spart[(size_t)ct * BL + idx];
        if (mask[idx] == 0) v -= 10000.f;
        vals[j] = v;
        mx = fmaxf(mx, v);
    }
    red[threadIdx.x] = mx;
    __syncthreads();
    for (int st = 128; st > 0; st >>= 1) {
        if (threadIdx.x < st) red[threadIdx.x] = fmaxf(red[threadIdx.x], red[threadIdx.x + st]);
        __syncthreads();
    }
    mx = red[0];
    __syncthreads();
    float se = 0.f;
#pragma unroll
    for (int j = 0; j < 8; j++) { vals[j] = __expf(vals[j] - mx); se += vals[j]; }
    red[threadIdx.x] = se;
    __syncthreads();
    for (int st = 128; st > 0; st >>= 1) {
        if (threadIdx.x < st) red[threadIdx.x] += red[threadIdx.x + st];
        __syncthreads();
    }
    float inv = 1.f / red[0];
#pragma unroll
    for (int j = 0; j < 8; j++)
        g_a[b * LLEN + threadIdx.x + j * 256] = vals[j] * inv;
}

// wsum split over 8 L-slices for occupancy; deterministic fixed partition.
__global__ void __launch_bounds__(256)
wsum_part_kernel(const float* __restrict__ h) {
    int b = blockIdx.y, sl = blockIdx.z;
    int c = blockIdx.x * 256 + threadIdx.x;
    int l0 = sl * 256;
    __shared__ float aw[256];
    aw[threadIdx.x] = g_a[b * LLEN + l0 + threadIdx.x];
    __syncthreads();
    const float* hp = h + ((size_t)b * LLEN + l0) * 1024 + c;
    float acc = 0.f;
#pragma unroll 8
    for (int l = 0; l < 256; l++)
        acc = fmaf(aw[l], hp[(size_t)l * 1024], acc);
    g_rpart[sl][b * 1024 + c] = acc;
}

__global__ void wsum_reduce_kernel(float* __restrict__ out) {
    int i = blockIdx.x * 256 + threadIdx.x;
    float acc = 0.f;
#pragma unroll
    for (int sl = 0; sl < 8; sl++) acc += g_rpart[sl][i];
    out[i] = acc;
}

// ---------------------------------------------------------------------------
extern "C" void kernel_launch(void* const* d_in, const int* in_sizes, int n_in,
                              void* d_out, int out_size) {
    const float* h    = (const float*)d_in[0];
    const int*   mask = (const int*)d_in[1];
    const float* ln_w = (const float*)d_in[2];
    const float* ln_b = (const float*)d_in[3];
    const float* v_w  = (const float*)d_in[4];
    const float* vq   = (const float*)d_in[5];
    float* out = (float*)d_out;

    cudaFuncSetAttribute(gemm_mma_kernel,
                         cudaFuncAttributeMaxDynamicSharedMemorySize, SMEM_BYTES);

    convert_h_kernel<<<65536, 256>>>(h);
    convert_w_kernel<<<1024, 256>>>(ln_w);
    bias_kernel<<<1024, 256>>>(ln_w, ln_b, vq);

    gemm_mma_kernel<<<dim3(8, 512), 256, SMEM_BYTES>>>(v_w);

    softmax_kernel<<<BATCH, 256>>>(mask);

    wsum_part_kernel<<<dim3(4, BATCH, 8), 256>>>(h);
    wsum_reduce_kernel<<<128, 256>>>(out);
}

// round 5
// speedup vs baseline: 3.0507x; 1.0010x over previous
#include <cuda_runtime.h>
#include <cuda_bf16.h>
#include <cstdint>

#define BATCH 32
#define LLEN  2048
#define BL    (BATCH * LLEN)      // 65536
#define NCTS  16                  // 16 partial s arrays (8 ntiles x 2 warp halves)

// ------------------------------- device scratch ----------------------------
__device__ __align__(16) __nv_bfloat16 g_h_hi[67108864];   // [BL][1024]
__device__ __align__(16) __nv_bfloat16 g_h_lo[67108864];
__device__ __align__(16) __nv_bfloat16 g_w_hi[1048576];    // [1024 N][1024 K]
__device__ __align__(16) __nv_bfloat16 g_w_lo[1048576];
__device__ float g_bias[1024];
__device__ float g_spart[NCTS * BL];
__device__ float g_a[BL];
__device__ float g_rpart[8][BATCH * 1024];

// ------------------------------- PTX helpers -------------------------------
__device__ __forceinline__ uint32_t smem_u32(const void* p) {
    uint32_t a;
    asm("{ .reg .u64 t; cvta.to.shared.u64 t, %1; cvt.u32.u64 %0, t; }" : "=r"(a) : "l"(p));
    return a;
}
__device__ __forceinline__ void cp16(uint32_t dst, const void* src) {
    asm volatile("cp.async.cg.shared.global [%0], [%1], 16;" :: "r"(dst), "l"(src));
}
#define LDSM4(r, addr) \
    asm volatile("ldmatrix.sync.aligned.m8n8.x4.shared.b16 {%0,%1,%2,%3}, [%4];" \
        : "=r"((r)[0]), "=r"((r)[1]), "=r"((r)[2]), "=r"((r)[3]) : "r"(addr))

__device__ __forceinline__ void mma16816(float* d, const uint32_t* a,
                                         uint32_t b0, uint32_t b1) {
    asm volatile("mma.sync.aligned.m16n8k16.row.col.f32.bf16.bf16.f32 "
        "{%0,%1,%2,%3}, {%4,%5,%6,%7}, {%8,%9}, {%0,%1,%2,%3};"
        : "+f"(d[0]), "+f"(d[1]), "+f"(d[2]), "+f"(d[3])
        : "r"(a[0]), "r"(a[1]), "r"(a[2]), "r"(a[3]), "r"(b0), "r"(b1));
}

__device__ __forceinline__ float tanh_fast(float x) {
    float e = __expf(2.f * x);
    return 1.f - 2.f / (e + 1.f);
}

// ------------------------------- GEMM constants ----------------------------
// Per stage (64 KB): A_hi 16K | A_lo 16K | B_hi 16K | B_lo 16K (128 rows x 128B, SW128)
#define NSTAGE 3
#define STAGE_STRIDE 65536
#define OFF_A_HI 0
#define OFF_A_LO 16384
#define OFF_B_HI 32768
#define OFF_B_LO 49152
#define OFF_SBIAS 196608
#define OFF_SVW   197120
#define SMEM_BYTES 197632

// Issue cp.asyncs for one K-chunk (64 bf16 wide) into stage `buf`.
// 256 threads: seg = tid&7 (16B), r0 = tid>>3 (0..31), rows r0 + v*32.
__device__ __forceinline__ void issue_chunk(uint32_t sb, int buf, int kc,
                                            int m0, int n0, int tid) {
    const int seg = tid & 7;
    const int r0  = tid >> 3;
    const size_t gbase = (size_t)kc * 64 + seg * 8;
    uint32_t sbase = sb + buf * STAGE_STRIDE;
#pragma unroll
    for (int v = 0; v < 4; v++) {
        int r = r0 + v * 32;
        uint32_t soff = (uint32_t)r * 128 + (uint32_t)((seg ^ (r & 7)) * 16);
        const size_t gA = (size_t)(m0 + r) * 1024 + gbase;
        const size_t gB = (size_t)(n0 + r) * 1024 + gbase;
        cp16(sbase + OFF_A_HI + soff, g_h_hi + gA);
        cp16(sbase + OFF_A_LO + soff, g_h_lo + gA);
        cp16(sbase + OFF_B_HI + soff, g_w_hi + gB);
        cp16(sbase + OFF_B_LO + soff, g_w_lo + gB);
    }
    asm volatile("cp.async.commit_group;" ::: "memory");
}

// ---------------------------------------------------------------------------
// HMMA GEMM: pre[128 rows, 128 cols] over K=1024, 3-term bf16 split,
// term-major MMA order (no accumulator RAW chains), 3-stage pipeline.
// grid (8 ntiles, 512 mtiles), 256 threads (8 warps: 4 M x 2 N).
// ---------------------------------------------------------------------------
__global__ void __launch_bounds__(256, 1)
gemm_mma_kernel(const float* __restrict__ v_w) {
    extern __shared__ char smem[];
    const uint32_t sb = smem_u32(smem);
    const int tid  = threadIdx.x;
    const int lane = tid & 31;
    const int warp = tid >> 5;
    const int wm   = warp & 3;        // 0..3: 32-row slice
    const int wn   = warp >> 2;       // 0..1: 64-col slice
    const int m0 = blockIdx.y * 128;
    const int n0 = blockIdx.x * 128;

    float* sbias = (float*)(smem + OFF_SBIAS);
    float* svw   = (float*)(smem + OFF_SVW);
    if (tid < 128) {
        sbias[tid] = g_bias[n0 + tid];
        svw[tid]   = v_w[n0 + tid];
    }

    float acc[2][8][4] = {};

    const int lrow  = lane & 15;
    const int lhalf = lane >> 4;

    issue_chunk(sb, 0, 0, m0, n0, tid);
    issue_chunk(sb, 1, 1, m0, n0, tid);
    issue_chunk(sb, 2, 2, m0, n0, tid);

    for (int c = 0; c < 16; c++) {
        const int buf = c % NSTAGE;
        if (c < 14)       asm volatile("cp.async.wait_group 2;" ::: "memory");
        else if (c == 14) asm volatile("cp.async.wait_group 1;" ::: "memory");
        else              asm volatile("cp.async.wait_group 0;" ::: "memory");
        __syncthreads();
        const uint32_t st = sb + buf * STAGE_STRIDE;

#pragma unroll
        for (int ks = 0; ks < 4; ks++) {
            // A fragments (2 m-steps, hi+lo)
            uint32_t a_hi[2][4], a_lo[2][4];
#pragma unroll
            for (int mi = 0; mi < 2; mi++) {
                int r = wm * 32 + mi * 16 + lrow;
                uint32_t boff = (uint32_t)(((ks * 2 + lhalf) ^ (r & 7)) * 16);
                uint32_t off = (uint32_t)r * 128 + boff;
                LDSM4(a_hi[mi], st + OFF_A_HI + off);
                LDSM4(a_lo[mi], st + OFF_A_LO + off);
            }
            // B fragments (4 groups of 16 n, hi+lo)
            uint32_t b_hi[4][4], b_lo[4][4];
#pragma unroll
            for (int ng = 0; ng < 4; ng++) {
                int r = wn * 64 + ng * 16 + lrow;
                uint32_t boff = (uint32_t)(((ks * 2 + lhalf) ^ (r & 7)) * 16);
                uint32_t off = (uint32_t)r * 128 + boff;
                LDSM4(b_hi[ng], st + OFF_B_HI + off);
                LDSM4(b_lo[ng], st + OFF_B_LO + off);
            }
            // Term-major: 16 independent MMAs between accumulator reuses.
#pragma unroll
            for (int mi = 0; mi < 2; mi++)
#pragma unroll
                for (int nt = 0; nt < 8; nt++) {
                    int ng = nt >> 1, hf = nt & 1;
                    mma16816(acc[mi][nt], a_hi[mi], b_hi[ng][hf], b_hi[ng][2 + hf]);
                }
#pragma unroll
            for (int mi = 0; mi < 2; mi++)
#pragma unroll
                for (int nt = 0; nt < 8; nt++) {
                    int ng = nt >> 1, hf = nt & 1;
                    mma16816(acc[mi][nt], a_hi[mi], b_lo[ng][hf], b_lo[ng][2 + hf]);
                }
#pragma unroll
            for (int mi = 0; mi < 2; mi++)
#pragma unroll
                for (int nt = 0; nt < 8; nt++) {
                    int ng = nt >> 1, hf = nt & 1;
                    mma16816(acc[mi][nt], a_lo[mi], b_hi[ng][hf], b_hi[ng][2 + hf]);
                }
        }
        __syncthreads();
        if (c < 13) issue_chunk(sb, buf, c + 3, m0, n0, tid);
    }

    // Epilogue: tanh(acc + bias) dot v_w, reduced over this warp's 64 cols.
    const int g = lane >> 2, tig = lane & 3;
#pragma unroll
    for (int mi = 0; mi < 2; mi++)
#pragma unroll
        for (int rg = 0; rg < 2; rg++) {
            float s = 0.f;
#pragma unroll
            for (int nt = 0; nt < 8; nt++) {
                int col = wn * 64 + nt * 8 + tig * 2;
                float p0 = acc[mi][nt][rg * 2 + 0] + sbias[col];
                float p1 = acc[mi][nt][rg * 2 + 1] + sbias[col + 1];
                s = fmaf(tanh_fast(p0), svw[col], s);
                s = fmaf(tanh_fast(p1), svw[col + 1], s);
            }
            s += __shfl_down_sync(0xffffffffu, s, 1, 4);
            s += __shfl_down_sync(0xffffffffu, s, 2, 4);
            if (tig == 0) {
                int row = m0 + wm * 32 + mi * 16 + rg * 8 + g;
                g_spart[(size_t)(blockIdx.x * 2 + wn) * BL + row] = s;
            }
        }
}

// ------------------------------- small kernels -----------------------------
__global__ void convert_h_kernel(const float* __restrict__ h) {
    size_t i = ((size_t)blockIdx.x * 256 + threadIdx.x) * 4;
    float4 v = *reinterpret_cast<const float4*>(h + i);
    union { __nv_bfloat16 b[4]; uint64_t u; } Hi, Lo;
    float xs[4] = {v.x, v.y, v.z, v.w};
#pragma unroll
    for (int j = 0; j < 4; j++) {
        __nv_bfloat16 hb = __float2bfloat16_rn(xs[j]);
        Hi.b[j] = hb;
        Lo.b[j] = __float2bfloat16_rn(xs[j] - __bfloat162float(hb));
    }
    *reinterpret_cast<uint64_t*>(g_h_hi + i) = Hi.u;
    *reinterpret_cast<uint64_t*>(g_h_lo + i) = Lo.u;
}

__global__ void convert_w_kernel(const float* __restrict__ ln_w) {
    size_t e = ((size_t)blockIdx.x * 256 + threadIdx.x) * 4;
    int n = (int)(e >> 10), k = (int)(e & 1023);
    float4 v = *reinterpret_cast<const float4*>(ln_w + (size_t)n * 2048 + k);
    union { __nv_bfloat16 b[4]; uint64_t u; } Hi, Lo;
    float xs[4] = {v.x, v.y, v.z, v.w};
#pragma unroll
    for (int j = 0; j < 4; j++) {
        __nv_bfloat16 hb = __float2bfloat16_rn(xs[j]);
        Hi.b[j] = hb;
        Lo.b[j] = __float2bfloat16_rn(xs[j] - __bfloat162float(hb));
    }
    *reinterpret_cast<uint64_t*>(g_w_hi + e) = Hi.u;
    *reinterpret_cast<uint64_t*>(g_w_lo + e) = Lo.u;
}

__global__ void bias_kernel(const float* __restrict__ ln_w,
                            const float* __restrict__ ln_b,
                            const float* __restrict__ vq) {
    int hh = blockIdx.x;
    const float* wrow = ln_w + (size_t)hh * 2048 + 1024;
    float sum = 0.f;
    for (int i = threadIdx.x; i < 1024; i += 256)
        sum = fmaf(wrow[i], vq[i], sum);
    __shared__ float red[256];
    red[threadIdx.x] = sum;
    __syncthreads();
    for (int st = 128; st > 0; st >>= 1) {
        if (threadIdx.x < st) red[threadIdx.x] += red[threadIdx.x + st];
        __syncthreads();
    }
    if (threadIdx.x == 0) g_bias[hh] = ln_b[hh] + red[0];
}

__global__ void softmax_kernel(const int* __restrict__ mask) {
    int b = blockIdx.x;
    __shared__ float red[256];
    float vals[8];
    float mx = -1e30f;
#pragma unroll
    for (int j = 0; j < 8; j++) {
        int idx = b * LLEN + threadIdx.x + j * 256;
        float v = 0.f;
#pragma unroll
        for (int ct = 0; ct < NCTS; ct++)
            v += g_spart[(size_t)ct * BL + idx];
        if (mask[idx] == 0) v -= 10000.f;
        vals[j] = v;
        mx = fmaxf(mx, v);
    }
    red[threadIdx.x] = mx;
    __syncthreads();
    for (int st = 128; st > 0; st >>= 1) {
        if (threadIdx.x < st) red[threadIdx.x] = fmaxf(red[threadIdx.x], red[threadIdx.x + st]);
        __syncthreads();
    }
    mx = red[0];
    __syncthreads();
    float se = 0.f;
#pragma unroll
    for (int j = 0; j < 8; j++) { vals[j] = __expf(vals[j] - mx); se += vals[j]; }
    red[threadIdx.x] = se;
    __syncthreads();
    for (int st = 128; st > 0; st >>= 1) {
        if (threadIdx.x < st) red[threadIdx.x] += red[threadIdx.x + st];
        __syncthreads();
    }
    float inv = 1.f / red[0];
#pragma unroll
    for (int j = 0; j < 8; j++)
        g_a[b * LLEN + threadIdx.x + j * 256] = vals[j] * inv;
}

// wsum split over 8 L-slices for occupancy; deterministic fixed partition.
__global__ void __launch_bounds__(256)
wsum_part_kernel(const float* __restrict__ h) {
    int b = blockIdx.y, sl = blockIdx.z;
    int c = blockIdx.x * 256 + threadIdx.x;
    int l0 = sl * 256;
    __shared__ float aw[256];
    aw[threadIdx.x] = g_a[b * LLEN + l0 + threadIdx.x];
    __syncthreads();
    const float* hp = h + ((size_t)b * LLEN + l0) * 1024 + c;
    float acc = 0.f;
#pragma unroll 8
    for (int l = 0; l < 256; l++)
        acc = fmaf(aw[l], hp[(size_t)l * 1024], acc);
    g_rpart[sl][b * 1024 + c] = acc;
}

__global__ void wsum_reduce_kernel(float* __restrict__ out) {
    int i = blockIdx.x * 256 + threadIdx.x;
    float acc = 0.f;
#pragma unroll
    for (int sl = 0; sl < 8; sl++) acc += g_rpart[sl][i];
    out[i] = acc;
}

// ---------------------------------------------------------------------------
extern "C" void kernel_launch(void* const* d_in, const int* in_sizes, int n_in,
                              void* d_out, int out_size) {
    const float* h    = (const float*)d_in[0];
    const int*   mask = (const int*)d_in[1];
    const float* ln_w = (const float*)d_in[2];
    const float* ln_b = (const float*)d_in[3];
    const float* v_w  = (const float*)d_in[4];
    const float* vq   = (const float*)d_in[5];
    float* out = (float*)d_out;

    cudaFuncSetAttribute(gemm_mma_kernel,
                         cudaFuncAttributeMaxDynamicSharedMemorySize, SMEM_BYTES);

    convert_h_kernel<<<65536, 256>>>(h);
    convert_w_kernel<<<1024, 256>>>(ln_w);
    bias_kernel<<<1024, 256>>>(ln_w, ln_b, vq);

    gemm_mma_kernel<<<dim3(8, 512), 256, SMEM_BYTES>>>(v_w);

    softmax_kernel<<<BATCH, 256>>>(mask);

    wsum_part_kernel<<<dim3(4, BATCH, 8), 256>>>(h);
    wsum_reduce_kernel<<<128, 256>>>(out);
}

// round 6
// speedup vs baseline: 4.0361x; 1.3230x over previous
#include <cuda_runtime.h>
#include <cuda_fp16.h>
#include <cstdint>

#define BATCH 32
#define LLEN  2048
#define BL    (BATCH * LLEN)      // 65536
#define NCTS  16                  // 16 partial s arrays (8 ntiles x 2 warp halves)

// ------------------------------- device scratch ----------------------------
__device__ __align__(16) __half g_h_hi[67108864];   // [BL][1024]
__device__ __align__(16) __half g_h_lo[67108864];
__device__ __align__(16) __half g_w_hi[1048576];    // [1024 N][1024 K]
__device__ float g_bias[1024];
__device__ float g_spart[NCTS * BL];
__device__ float g_a[BL];
__device__ float g_rpart[8][BATCH * 1024];

// ------------------------------- PTX helpers -------------------------------
__device__ __forceinline__ uint32_t smem_u32(const void* p) {
    uint32_t a;
    asm("{ .reg .u64 t; cvta.to.shared.u64 t, %1; cvt.u32.u64 %0, t; }" : "=r"(a) : "l"(p));
    return a;
}
__device__ __forceinline__ void cp16(uint32_t dst, const void* src) {
    asm volatile("cp.async.cg.shared.global [%0], [%1], 16;" :: "r"(dst), "l"(src));
}
#define LDSM4(r, addr) \
    asm volatile("ldmatrix.sync.aligned.m8n8.x4.shared.b16 {%0,%1,%2,%3}, [%4];" \
        : "=r"((r)[0]), "=r"((r)[1]), "=r"((r)[2]), "=r"((r)[3]) : "r"(addr))

__device__ __forceinline__ void mma16816h(float* d, const uint32_t* a,
                                          uint32_t b0, uint32_t b1) {
    asm volatile("mma.sync.aligned.m16n8k16.row.col.f32.f16.f16.f32 "
        "{%0,%1,%2,%3}, {%4,%5,%6,%7}, {%8,%9}, {%0,%1,%2,%3};"
        : "+f"(d[0]), "+f"(d[1]), "+f"(d[2]), "+f"(d[3])
        : "r"(a[0]), "r"(a[1]), "r"(a[2]), "r"(a[3]), "r"(b0), "r"(b1));
}

__device__ __forceinline__ float tanh_fast(float x) {
    float e = __expf(2.f * x);
    return 1.f - 2.f / (e + 1.f);
}

// ------------------------------- GEMM constants ----------------------------
// Per stage (48 KB): A_hi 16K | A_lo 16K | B_hi 16K (128 rows x 128 B, SW128)
#define NSTAGE 4
#define STAGE_STRIDE 49152
#define OFF_A_HI 0
#define OFF_A_LO 16384
#define OFF_B_HI 32768
#define OFF_SBIAS 196608
#define OFF_SVW   197120
#define SMEM_BYTES 197632

// Issue cp.asyncs for one K-chunk (64 fp16 wide) into stage `buf`.
// 256 threads: seg = tid&7 (16B), r0 = tid>>3 (0..31), rows r0 + v*32.
__device__ __forceinline__ void issue_chunk(uint32_t sb, int buf, int kc,
                                            int m0, int n0, int tid) {
    const int seg = tid & 7;
    const int r0  = tid >> 3;
    const size_t gbase = (size_t)kc * 64 + seg * 8;
    uint32_t sbase = sb + buf * STAGE_STRIDE;
#pragma unroll
    for (int v = 0; v < 4; v++) {
        int r = r0 + v * 32;
        uint32_t soff = (uint32_t)r * 128 + (uint32_t)((seg ^ (r & 7)) * 16);
        const size_t gA = (size_t)(m0 + r) * 1024 + gbase;
        const size_t gB = (size_t)(n0 + r) * 1024 + gbase;
        cp16(sbase + OFF_A_HI + soff, g_h_hi + gA);
        cp16(sbase + OFF_A_LO + soff, g_h_lo + gA);
        cp16(sbase + OFF_B_HI + soff, g_w_hi + gB);
    }
    asm volatile("cp.async.commit_group;" ::: "memory");
}

// ---------------------------------------------------------------------------
// HMMA GEMM: pre[128 rows, 128 cols] over K=1024 in fp16 2-term split
// ((h_hi + h_lo) x fp16(W), fp32 accumulate). 4-stage cp.async pipeline,
// double-buffered ldmatrix fragments (prefetch ks+1 during ks MMAs).
// grid (8 ntiles, 512 mtiles), 256 threads (8 warps: 4 M x 2 N).
// ---------------------------------------------------------------------------
__global__ void __launch_bounds__(256, 1)
gemm_mma_kernel(const float* __restrict__ v_w) {
    extern __shared__ char smem[];
    const uint32_t sb = smem_u32(smem);
    const int tid  = threadIdx.x;
    const int lane = tid & 31;
    const int warp = tid >> 5;
    const int wm   = warp & 3;        // 0..3: 32-row slice
    const int wn   = warp >> 2;       // 0..1: 64-col slice
    const int m0 = blockIdx.y * 128;
    const int n0 = blockIdx.x * 128;

    float* sbias = (float*)(smem + OFF_SBIAS);
    float* svw   = (float*)(smem + OFF_SVW);
    if (tid < 128) {
        sbias[tid] = g_bias[n0 + tid];
        svw[tid]   = v_w[n0 + tid];
    }

    const int lrow  = lane & 15;
    const int lhalf = lane >> 4;

    // Hoisted swizzle bases: offset(ks) = rX + (((ks*2+lhalf)<<4) ^ r7X)
    int rA[2], r7A[2], rB[4], r7B[4];
#pragma unroll
    for (int mi = 0; mi < 2; mi++) {
        int r = wm * 32 + mi * 16 + lrow;
        rA[mi] = r * 128; r7A[mi] = (r & 7) * 16;
    }
#pragma unroll
    for (int ng = 0; ng < 4; ng++) {
        int r = wn * 64 + ng * 16 + lrow;
        rB[ng] = r * 128; r7B[ng] = (r & 7) * 16;
    }

    float acc[2][8][4] = {};
    uint32_t aF[2][2][2][4];   // [regbuf][mi][hi/lo][4]
    uint32_t bF[2][4][4];      // [regbuf][ng][4]

#define LOAD_FRAGS(RB, KS) do {                                           \
    uint32_t kk = (uint32_t)(((KS) * 2 + lhalf) * 16);                    \
    _Pragma("unroll")                                                     \
    for (int mi = 0; mi < 2; mi++) {                                      \
        uint32_t off = (uint32_t)rA[mi] + (kk ^ (uint32_t)r7A[mi]);       \
        LDSM4(aF[RB][mi][0], st + OFF_A_HI + off);                        \
        LDSM4(aF[RB][mi][1], st + OFF_A_LO + off);                        \
    }                                                                     \
    _Pragma("unroll")                                                     \
    for (int ng = 0; ng < 4; ng++) {                                      \
        uint32_t off = (uint32_t)rB[ng] + (kk ^ (uint32_t)r7B[ng]);       \
        LDSM4(bF[RB][ng], st + OFF_B_HI + off);                           \
    }                                                                     \
} while (0)

#define MMA_STEP(RB) do {                                                 \
    _Pragma("unroll")                                                     \
    for (int mi = 0; mi < 2; mi++)                                        \
        _Pragma("unroll")                                                 \
        for (int nt = 0; nt < 8; nt++) {                                  \
            int ng = nt >> 1, hf = nt & 1;                                \
            mma16816h(acc[mi][nt], aF[RB][mi][0],                         \
                      bF[RB][ng][hf], bF[RB][ng][2 + hf]);                \
        }                                                                 \
    _Pragma("unroll")                                                     \
    for (int mi = 0; mi < 2; mi++)                                        \
        _Pragma("unroll")                                                 \
        for (int nt = 0; nt < 8; nt++) {                                  \
            int ng = nt >> 1, hf = nt & 1;                                \
            mma16816h(acc[mi][nt], aF[RB][mi][1],                         \
                      bF[RB][ng][hf], bF[RB][ng][2 + hf]);                \
        }                                                                 \
} while (0)

    issue_chunk(sb, 0, 0, m0, n0, tid);
    issue_chunk(sb, 1, 1, m0, n0, tid);
    issue_chunk(sb, 2, 2, m0, n0, tid);
    issue_chunk(sb, 3, 3, m0, n0, tid);

    for (int c = 0; c < 16; c++) {
        const int buf = c & 3;
        if (c < 13)       asm volatile("cp.async.wait_group 3;" ::: "memory");
        else if (c == 13) asm volatile("cp.async.wait_group 2;" ::: "memory");
        else if (c == 14) asm volatile("cp.async.wait_group 1;" ::: "memory");
        else              asm volatile("cp.async.wait_group 0;" ::: "memory");
        __syncthreads();
        const uint32_t st = sb + buf * STAGE_STRIDE;

        // software-pipelined fragment loads: load ks+1 before MMAs of ks
        LOAD_FRAGS(0, 0);
        LOAD_FRAGS(1, 1);
        MMA_STEP(0);
        LOAD_FRAGS(0, 2);
        MMA_STEP(1);
        LOAD_FRAGS(1, 3);
        MMA_STEP(0);
        MMA_STEP(1);

        __syncthreads();
        if (c < 12) issue_chunk(sb, buf, c + 4, m0, n0, tid);
    }

    // Epilogue: tanh(acc + bias) dot v_w, reduced over this warp's 64 cols.
    const int g = lane >> 2, tig = lane & 3;
#pragma unroll
    for (int mi = 0; mi < 2; mi++)
#pragma unroll
        for (int rg = 0; rg < 2; rg++) {
            float s = 0.f;
#pragma unroll
            for (int nt = 0; nt < 8; nt++) {
                int col = wn * 64 + nt * 8 + tig * 2;
                float p0 = acc[mi][nt][rg * 2 + 0] + sbias[col];
                float p1 = acc[mi][nt][rg * 2 + 1] + sbias[col + 1];
                s = fmaf(tanh_fast(p0), svw[col], s);
                s = fmaf(tanh_fast(p1), svw[col + 1], s);
            }
            s += __shfl_down_sync(0xffffffffu, s, 1, 4);
            s += __shfl_down_sync(0xffffffffu, s, 2, 4);
            if (tig == 0) {
                int row = m0 + wm * 32 + mi * 16 + rg * 8 + g;
                g_spart[(size_t)(blockIdx.x * 2 + wn) * BL + row] = s;
            }
        }
}

// ------------------------------- small kernels -----------------------------
__global__ void convert_h_kernel(const float* __restrict__ h) {
    size_t i = ((size_t)blockIdx.x * 256 + threadIdx.x) * 4;
    float4 v = *reinterpret_cast<const float4*>(h + i);
    union { __half b[4]; uint64_t u; } Hi, Lo;
    float xs[4] = {v.x, v.y, v.z, v.w};
#pragma unroll
    for (int j = 0; j < 4; j++) {
        __half hb = __float2half_rn(xs[j]);
        Hi.b[j] = hb;
        Lo.b[j] = __float2half_rn(xs[j] - __half2float(hb));
    }
    *reinterpret_cast<uint64_t*>(g_h_hi + i) = Hi.u;
    *reinterpret_cast<uint64_t*>(g_h_lo + i) = Lo.u;
}

__global__ void convert_w_kernel(const float* __restrict__ ln_w) {
    size_t e = ((size_t)blockIdx.x * 256 + threadIdx.x) * 4;
    int n = (int)(e >> 10), k = (int)(e & 1023);
    float4 v = *reinterpret_cast<const float4*>(ln_w + (size_t)n * 2048 + k);
    union { __half b[4]; uint64_t u; } Hi;
    float xs[4] = {v.x, v.y, v.z, v.w};
#pragma unroll
    for (int j = 0; j < 4; j++)
        Hi.b[j] = __float2half_rn(xs[j]);
    *reinterpret_cast<uint64_t*>(g_w_hi + e) = Hi.u;
}

__global__ void bias_kernel(const float* __restrict__ ln_w,
                            const float* __restrict__ ln_b,
                            const float* __restrict__ vq) {
    int hh = blockIdx.x;
    const float* wrow = ln_w + (size_t)hh * 2048 + 1024;
    float sum = 0.f;
    for (int i = threadIdx.x; i < 1024; i += 256)
        sum = fmaf(wrow[i], vq[i], sum);
    __shared__ float red[256];
    red[threadIdx.x] = sum;
    __syncthreads();
    for (int st = 128; st > 0; st >>= 1) {
        if (threadIdx.x < st) red[threadIdx.x] += red[threadIdx.x + st];
        __syncthreads();
    }
    if (threadIdx.x == 0) g_bias[hh] = ln_b[hh] + red[0];
}

__global__ void softmax_kernel(const int* __restrict__ mask) {
    int b = blockIdx.x;
    __shared__ float red[256];
    float vals[8];
    float mx = -1e30f;
#pragma unroll
    for (int j = 0; j < 8; j++) {
        int idx = b * LLEN + threadIdx.x + j * 256;
        float v = 0.f;
#pragma unroll
        for (int ct = 0; ct < NCTS; ct++)
            v += g_spart[(size_t)ct * BL + idx];
        if (mask[idx] == 0) v -= 10000.f;
        vals[j] = v;
        mx = fmaxf(mx, v);
    }
    red[threadIdx.x] = mx;
    __syncthreads();
    for (int st = 128; st > 0; st >>= 1) {
        if (threadIdx.x < st) red[threadIdx.x] = fmaxf(red[threadIdx.x], red[threadIdx.x + st]);
        __syncthreads();
    }
    mx = red[0];
    __syncthreads();
    float se = 0.f;
#pragma unroll
    for (int j = 0; j < 8; j++) { vals[j] = __expf(vals[j] - mx); se += vals[j]; }
    red[threadIdx.x] = se;
    __syncthreads();
    for (int st = 128; st > 0; st >>= 1) {
        if (threadIdx.x < st) red[threadIdx.x] += red[threadIdx.x + st];
        __syncthreads();
    }
    float inv = 1.f / red[0];
#pragma unroll
    for (int j = 0; j < 8; j++)
        g_a[b * LLEN + threadIdx.x + j * 256] = vals[j] * inv;
}

// wsum split over 8 L-slices for occupancy; deterministic fixed partition.
__global__ void __launch_bounds__(256)
wsum_part_kernel(const float* __restrict__ h) {
    int b = blockIdx.y, sl = blockIdx.z;
    int c = blockIdx.x * 256 + threadIdx.x;
    int l0 = sl * 256;
    __shared__ float aw[256];
    aw[threadIdx.x] = g_a[b * LLEN + l0 + threadIdx.x];
    __syncthreads();
    const float* hp = h + ((size_t)b * LLEN + l0) * 1024 + c;
    float acc = 0.f;
#pragma unroll 8
    for (int l = 0; l < 256; l++)
        acc = fmaf(aw[l], hp[(size_t)l * 1024], acc);
    g_rpart[sl][b * 1024 + c] = acc;
}

__global__ void wsum_reduce_kernel(float* __restrict__ out) {
    int i = blockIdx.x * 256 + threadIdx.x;
    float acc = 0.f;
#pragma unroll
    for (int sl = 0; sl < 8; sl++) acc += g_rpart[sl][i];
    out[i] = acc;
}

// ---------------------------------------------------------------------------
extern "C" void kernel_launch(void* const* d_in, const int* in_sizes, int n_in,
                              void* d_out, int out_size) {
    const float* h    = (const float*)d_in[0];
    const int*   mask = (const int*)d_in[1];
    const float* ln_w = (const float*)d_in[2];
    const float* ln_b = (const float*)d_in[3];
    const float* v_w  = (const float*)d_in[4];
    const float* vq   = (const float*)d_in[5];
    float* out = (float*)d_out;

    cudaFuncSetAttribute(gemm_mma_kernel,
                         cudaFuncAttributeMaxDynamicSharedMemorySize, SMEM_BYTES);

    convert_h_kernel<<<65536, 256>>>(h);
    convert_w_kernel<<<1024, 256>>>(ln_w);
    bias_kernel<<<1024, 256>>>(ln_w, ln_b, vq);

    gemm_mma_kernel<<<dim3(8, 512), 256, SMEM_BYTES>>>(v_w);

    softmax_kernel<<<BATCH, 256>>>(mask);

    wsum_part_kernel<<<dim3(4, BATCH, 8), 256>>>(h);
    wsum_reduce_kernel<<<128, 256>>>(out);
}

// round 7
// speedup vs baseline: 4.6751x; 1.1583x over previous
#include <cuda_runtime.h>
#include <cuda_fp16.h>
#include <cstdint>

#define BATCH 32
#define LLEN  2048
#define BL    (BATCH * LLEN)      // 65536
#define NCTS  16                  // 16 partial s arrays (8 ntiles x 2 warp halves)

// ------------------------------- device scratch ----------------------------
__device__ __align__(16) __half g_h_hi[67108864];   // [BL][1024]
__device__ __align__(16) __half g_h_lo[67108864];
__device__ __align__(16) __half g_w_hi[1048576];    // [1024 N][1024 K]
__device__ float g_bias[1024];
__device__ float g_spart[NCTS * BL];
__device__ float g_a[BL];
__device__ float g_rpart[8][BATCH * 1024];

// ------------------------------- PTX helpers -------------------------------
__device__ __forceinline__ uint32_t smem_u32(const void* p) {
    uint32_t a;
    asm("{ .reg .u64 t; cvta.to.shared.u64 t, %1; cvt.u32.u64 %0, t; }" : "=r"(a) : "l"(p));
    return a;
}
__device__ __forceinline__ void cp16(uint32_t dst, const void* src) {
    asm volatile("cp.async.cg.shared.global [%0], [%1], 16;" :: "r"(dst), "l"(src));
}
#define LDSM4(r, addr) \
    asm volatile("ldmatrix.sync.aligned.m8n8.x4.shared.b16 {%0,%1,%2,%3}, [%4];" \
        : "=r"((r)[0]), "=r"((r)[1]), "=r"((r)[2]), "=r"((r)[3]) : "r"(addr))

__device__ __forceinline__ void mma16816h(float* d, const uint32_t* a,
                                          uint32_t b0, uint32_t b1) {
    asm volatile("mma.sync.aligned.m16n8k16.row.col.f32.f16.f16.f32 "
        "{%0,%1,%2,%3}, {%4,%5,%6,%7}, {%8,%9}, {%0,%1,%2,%3};"
        : "+f"(d[0]), "+f"(d[1]), "+f"(d[2]), "+f"(d[3])
        : "r"(a[0]), "r"(a[1]), "r"(a[2]), "r"(a[3]), "r"(b0), "r"(b1));
}

__device__ __forceinline__ float tanh_fast(float x) {
    float e = __expf(2.f * x);
    return 1.f - 2.f / (e + 1.f);
}

// ------------------------------- GEMM constants ----------------------------
// Per stage (48 KB): A_hi 16K | A_lo 16K | B_hi 16K (128 rows x 128 B, SW128)
// 2 stages x 48 KB + 1 KB params = 97 KB -> 2 CTAs/SM.
#define STAGE_STRIDE 49152
#define OFF_A_HI 0
#define OFF_A_LO 16384
#define OFF_B_HI 32768
#define OFF_SBIAS 98304
#define OFF_SVW   98816
#define SMEM_BYTES 99328

// Issue cp.asyncs for one K-chunk (64 fp16 wide) into stage `buf`.
// 256 threads: seg = tid&7 (16B), r0 = tid>>3 (0..31), rows r0 + v*32.
__device__ __forceinline__ void issue_chunk(uint32_t sb, int buf, int kc,
                                            int m0, int n0, int tid) {
    const int seg = tid & 7;
    const int r0  = tid >> 3;
    const size_t gbase = (size_t)kc * 64 + seg * 8;
    uint32_t sbase = sb + buf * STAGE_STRIDE;
#pragma unroll
    for (int v = 0; v < 4; v++) {
        int r = r0 + v * 32;
        uint32_t soff = (uint32_t)r * 128 + (uint32_t)((seg ^ (r & 7)) * 16);
        const size_t gA = (size_t)(m0 + r) * 1024 + gbase;
        const size_t gB = (size_t)(n0 + r) * 1024 + gbase;
        cp16(sbase + OFF_A_HI + soff, g_h_hi + gA);
        cp16(sbase + OFF_A_LO + soff, g_h_lo + gA);
        cp16(sbase + OFF_B_HI + soff, g_w_hi + gB);
    }
    asm volatile("cp.async.commit_group;" ::: "memory");
}

// ---------------------------------------------------------------------------
// HMMA GEMM: pre[128 rows, 128 cols] over K=1024 in fp16 2-term split
// ((h_hi + h_lo) x fp16(W), fp32 accumulate). 2-stage single-sync pipeline,
// 2 CTAs/SM. grid (8 ntiles, 512 mtiles), 256 threads (8 warps: 4 M x 2 N).
// ---------------------------------------------------------------------------
__global__ void __launch_bounds__(256, 2)
gemm_mma_kernel(const float* __restrict__ v_w) {
    extern __shared__ char smem[];
    const uint32_t sb = smem_u32(smem);
    const int tid  = threadIdx.x;
    const int lane = tid & 31;
    const int warp = tid >> 5;
    const int wm   = warp & 3;        // 0..3: 32-row slice
    const int wn   = warp >> 2;       // 0..1: 64-col slice
    const int m0 = blockIdx.y * 128;
    const int n0 = blockIdx.x * 128;

    float* sbias = (float*)(smem + OFF_SBIAS);
    float* svw   = (float*)(smem + OFF_SVW);
    if (tid < 128) {
        sbias[tid] = g_bias[n0 + tid];
        svw[tid]   = v_w[n0 + tid];
    }

    const int lrow  = lane & 15;
    const int lhalf = lane >> 4;

    // Hoisted swizzle bases: offset(ks) = rX + (((ks*2+lhalf)<<4) ^ r7X)
    int rA[2], r7A[2], rB[4], r7B[4];
#pragma unroll
    for (int mi = 0; mi < 2; mi++) {
        int r = wm * 32 + mi * 16 + lrow;
        rA[mi] = r * 128; r7A[mi] = (r & 7) * 16;
    }
#pragma unroll
    for (int ng = 0; ng < 4; ng++) {
        int r = wn * 64 + ng * 16 + lrow;
        rB[ng] = r * 128; r7B[ng] = (r & 7) * 16;
    }

    float acc[2][8][4] = {};

    // prologue: stage 0 only (single-sync 2-stage pipeline)
    issue_chunk(sb, 0, 0, m0, n0, tid);

    for (int c = 0; c < 16; c++) {
        const int buf = c & 1;
        asm volatile("cp.async.wait_group 0;" ::: "memory");  // chunk c resident
        __syncthreads();                                      // frees stage (c-1)&1
        if (c < 15) issue_chunk(sb, buf ^ 1, c + 1, m0, n0, tid);
        const uint32_t st = sb + buf * STAGE_STRIDE;

#pragma unroll
        for (int ks = 0; ks < 4; ks++) {
            uint32_t kk = (uint32_t)((ks * 2 + lhalf) * 16);
            uint32_t aF[2][2][4];   // [mi][hi/lo]
            uint32_t bF[4][4];
#pragma unroll
            for (int mi = 0; mi < 2; mi++) {
                uint32_t off = (uint32_t)rA[mi] + (kk ^ (uint32_t)r7A[mi]);
                LDSM4(aF[mi][0], st + OFF_A_HI + off);
                LDSM4(aF[mi][1], st + OFF_A_LO + off);
            }
#pragma unroll
            for (int ng = 0; ng < 4; ng++) {
                uint32_t off = (uint32_t)rB[ng] + (kk ^ (uint32_t)r7B[ng]);
                LDSM4(bF[ng], st + OFF_B_HI + off);
            }
#pragma unroll
            for (int mi = 0; mi < 2; mi++)
#pragma unroll
                for (int nt = 0; nt < 8; nt++) {
                    int ng = nt >> 1, hf = nt & 1;
                    mma16816h(acc[mi][nt], aF[mi][0], bF[ng][hf], bF[ng][2 + hf]);
                }
#pragma unroll
            for (int mi = 0; mi < 2; mi++)
#pragma unroll
                for (int nt = 0; nt < 8; nt++) {
                    int ng = nt >> 1, hf = nt & 1;
                    mma16816h(acc[mi][nt], aF[mi][1], bF[ng][hf], bF[ng][2 + hf]);
                }
        }
    }

    // Epilogue: tanh(acc + bias) dot v_w, reduced over this warp's 64 cols.
    const int g = lane >> 2, tig = lane & 3;
#pragma unroll
    for (int mi = 0; mi < 2; mi++)
#pragma unroll
        for (int rg = 0; rg < 2; rg++) {
            float s = 0.f;
#pragma unroll
            for (int nt = 0; nt < 8; nt++) {
                int col = wn * 64 + nt * 8 + tig * 2;
                float p0 = acc[mi][nt][rg * 2 + 0] + sbias[col];
                float p1 = acc[mi][nt][rg * 2 + 1] + sbias[col + 1];
                s = fmaf(tanh_fast(p0), svw[col], s);
                s = fmaf(tanh_fast(p1), svw[col + 1], s);
            }
            s += __shfl_down_sync(0xffffffffu, s, 1, 4);
            s += __shfl_down_sync(0xffffffffu, s, 2, 4);
            if (tig == 0) {
                int row = m0 + wm * 32 + mi * 16 + rg * 8 + g;
                g_spart[(size_t)(blockIdx.x * 2 + wn) * BL + row] = s;
            }
        }
}

// ------------------------------- small kernels -----------------------------
__global__ void convert_h_kernel(const float* __restrict__ h) {
    size_t i = ((size_t)blockIdx.x * 256 + threadIdx.x) * 4;
    float4 v = *reinterpret_cast<const float4*>(h + i);
    union { __half b[4]; uint64_t u; } Hi, Lo;
    float xs[4] = {v.x, v.y, v.z, v.w};
#pragma unroll
    for (int j = 0; j < 4; j++) {
        __half hb = __float2half_rn(xs[j]);
        Hi.b[j] = hb;
        Lo.b[j] = __float2half_rn(xs[j] - __half2float(hb));
    }
    *reinterpret_cast<uint64_t*>(g_h_hi + i) = Hi.u;
    *reinterpret_cast<uint64_t*>(g_h_lo + i) = Lo.u;
}

__global__ void convert_w_kernel(const float* __restrict__ ln_w) {
    size_t e = ((size_t)blockIdx.x * 256 + threadIdx.x) * 4;
    int n = (int)(e >> 10), k = (int)(e & 1023);
    float4 v = *reinterpret_cast<const float4*>(ln_w + (size_t)n * 2048 + k);
    union { __half b[4]; uint64_t u; } Hi;
    float xs[4] = {v.x, v.y, v.z, v.w};
#pragma unroll
    for (int j = 0; j < 4; j++)
        Hi.b[j] = __float2half_rn(xs[j]);
    *reinterpret_cast<uint64_t*>(g_w_hi + e) = Hi.u;
}

__global__ void bias_kernel(const float* __restrict__ ln_w,
                            const float* __restrict__ ln_b,
                            const float* __restrict__ vq) {
    int hh = blockIdx.x;
    const float* wrow = ln_w + (size_t)hh * 2048 + 1024;
    float sum = 0.f;
    for (int i = threadIdx.x; i < 1024; i += 256)
        sum = fmaf(wrow[i], vq[i], sum);
    __shared__ float red[256];
    red[threadIdx.x] = sum;
    __syncthreads();
    for (int st = 128; st > 0; st >>= 1) {
        if (threadIdx.x < st) red[threadIdx.x] += red[threadIdx.x + st];
        __syncthreads();
    }
    if (threadIdx.x == 0) g_bias[hh] = ln_b[hh] + red[0];
}

__global__ void softmax_kernel(const int* __restrict__ mask) {
    int b = blockIdx.x;
    __shared__ float red[256];
    float vals[8];
    float mx = -1e30f;
#pragma unroll
    for (int j = 0; j < 8; j++) {
        int idx = b * LLEN + threadIdx.x + j * 256;
        float v = 0.f;
#pragma unroll
        for (int ct = 0; ct < NCTS; ct++)
            v += g_spart[(size_t)ct * BL + idx];
        if (mask[idx] == 0) v -= 10000.f;
        vals[j] = v;
        mx = fmaxf(mx, v);
    }
    red[threadIdx.x] = mx;
    __syncthreads();
    for (int st = 128; st > 0; st >>= 1) {
        if (threadIdx.x < st) red[threadIdx.x] = fmaxf(red[threadIdx.x], red[threadIdx.x + st]);
        __syncthreads();
    }
    mx = red[0];
    __syncthreads();
    float se = 0.f;
#pragma unroll
    for (int j = 0; j < 8; j++) { vals[j] = __expf(vals[j] - mx); se += vals[j]; }
    red[threadIdx.x] = se;
    __syncthreads();
    for (int st = 128; st > 0; st >>= 1) {
        if (threadIdx.x < st) red[threadIdx.x] += red[threadIdx.x + st];
        __syncthreads();
    }
    float inv = 1.f / red[0];
#pragma unroll
    for (int j = 0; j < 8; j++)
        g_a[b * LLEN + threadIdx.x + j * 256] = vals[j] * inv;
}

// wsum split over 8 L-slices for occupancy; deterministic fixed partition.
__global__ void __launch_bounds__(256)
wsum_part_kernel(const float* __restrict__ h) {
    int b = blockIdx.y, sl = blockIdx.z;
    int c = blockIdx.x * 256 + threadIdx.x;
    int l0 = sl * 256;
    __shared__ float aw[256];
    aw[threadIdx.x] = g_a[b * LLEN + l0 + threadIdx.x];
    __syncthreads();
    const float* hp = h + ((size_t)b * LLEN + l0) * 1024 + c;
    float acc = 0.f;
#pragma unroll 8
    for (int l = 0; l < 256; l++)
        acc = fmaf(aw[l], hp[(size_t)l * 1024], acc);
    g_rpart[sl][b * 1024 + c] = acc;
}

__global__ void wsum_reduce_kernel(float* __restrict__ out) {
    int i = blockIdx.x * 256 + threadIdx.x;
    float acc = 0.f;
#pragma unroll
    for (int sl = 0; sl < 8; sl++) acc += g_rpart[sl][i];
    out[i] = acc;
}

// ---------------------------------------------------------------------------
extern "C" void kernel_launch(void* const* d_in, const int* in_sizes, int n_in,
                              void* d_out, int out_size) {
    const float* h    = (const float*)d_in[0];
    const int*   mask = (const int*)d_in[1];
    const float* ln_w = (const float*)d_in[2];
    const float* ln_b = (const float*)d_in[3];
    const float* v_w  = (const float*)d_in[4];
    const float* vq   = (const float*)d_in[5];
    float* out = (float*)d_out;

    cudaFuncSetAttribute(gemm_mma_kernel,
                         cudaFuncAttributeMaxDynamicSharedMemorySize, SMEM_BYTES);

    convert_h_kernel<<<65536, 256>>>(h);
    convert_w_kernel<<<1024, 256>>>(ln_w);
    bias_kernel<<<1024, 256>>>(ln_w, ln_b, vq);

    gemm_mma_kernel<<<dim3(8, 512), 256, SMEM_BYTES>>>(v_w);

    softmax_kernel<<<BATCH, 256>>>(mask);

    wsum_part_kernel<<<dim3(4, BATCH, 8), 256>>>(h);
    wsum_reduce_kernel<<<128, 256>>>(out);
}

// round 8
// speedup vs baseline: 7.8819x; 1.6859x over previous
#include <cuda_runtime.h>
#include <cuda_fp16.h>
#include <cstdint>

#define BATCH 32
#define LLEN  2048
#define BL    (BATCH * LLEN)      // 65536
#define NCTS  16                  // 16 partial s arrays (8 ntiles x 2 warp halves)

// ------------------------------- device scratch ----------------------------
__device__ __align__(16) __half g_h_hi[67108864];   // [BL][1024] fp16(h)
__device__ __align__(16) __half g_w_hi[1048576];    // [1024 N][1024 K] fp16(W)
__device__ float g_bias[1024];
__device__ float g_spart[NCTS * BL];
__device__ float g_a[BL];
__device__ float g_rpart[8][BATCH * 1024];

// ------------------------------- PTX helpers -------------------------------
__device__ __forceinline__ uint32_t smem_u32(const void* p) {
    uint32_t a;
    asm("{ .reg .u64 t; cvta.to.shared.u64 t, %1; cvt.u32.u64 %0, t; }" : "=r"(a) : "l"(p));
    return a;
}
__device__ __forceinline__ void cp16(uint32_t dst, const void* src) {
    asm volatile("cp.async.cg.shared.global [%0], [%1], 16;" :: "r"(dst), "l"(src));
}
#define LDSM4(r, addr) \
    asm volatile("ldmatrix.sync.aligned.m8n8.x4.shared.b16 {%0,%1,%2,%3}, [%4];" \
        : "=r"((r)[0]), "=r"((r)[1]), "=r"((r)[2]), "=r"((r)[3]) : "r"(addr))

__device__ __forceinline__ void mma16816h(float* d, const uint32_t* a,
                                          uint32_t b0, uint32_t b1) {
    asm volatile("mma.sync.aligned.m16n8k16.row.col.f32.f16.f16.f32 "
        "{%0,%1,%2,%3}, {%4,%5,%6,%7}, {%8,%9}, {%0,%1,%2,%3};"
        : "+f"(d[0]), "+f"(d[1]), "+f"(d[2]), "+f"(d[3])
        : "r"(a[0]), "r"(a[1]), "r"(a[2]), "r"(a[3]), "r"(b0), "r"(b1));
}

__device__ __forceinline__ float tanh_fast(float x) {
    float e = __expf(2.f * x);
    return 1.f - 2.f / (e + 1.f);
}

// ------------------------------- GEMM constants ----------------------------
// Per stage (32 KB): A 16K | B 16K (128 rows x 128 B, SW128). 3 stages = 96 KB
// + 1 KB params -> 2 CTAs/SM.
#define STAGE_STRIDE 32768
#define OFF_A 0
#define OFF_B 16384
#define OFF_SBIAS 98304
#define OFF_SVW   98816
#define SMEM_BYTES 99328

// ---------------------------------------------------------------------------
// HMMA GEMM: pre[128 rows, 128 cols] over K=1024, single-term fp16
// (fp16(h) x fp16(W), fp32 accumulate). 3-stage single-sync pipeline,
// 2 CTAs/SM. grid (8 ntiles, 512 mtiles), 256 threads (8 warps: 4 M x 2 N).
// ---------------------------------------------------------------------------
__global__ void __launch_bounds__(256, 2)
gemm_mma_kernel(const float* __restrict__ v_w) {
    extern __shared__ char smem[];
    const uint32_t sb = smem_u32(smem);
    const int tid  = threadIdx.x;
    const int lane = tid & 31;
    const int warp = tid >> 5;
    const int wm   = warp & 3;        // 0..3: 32-row slice
    const int wn   = warp >> 2;       // 0..1: 64-col slice
    const int m0 = blockIdx.y * 128;
    const int n0 = blockIdx.x * 128;

    float* sbias = (float*)(smem + OFF_SBIAS);
    float* svw   = (float*)(smem + OFF_SVW);
    if (tid < 128) {
        sbias[tid] = g_bias[n0 + tid];
        svw[tid]   = v_w[n0 + tid];
    }

    // Producer state: hoisted pointers, advanced +64 halves per chunk.
    const int seg = tid & 7;
    const int r0  = tid >> 3;
    const __half* pA[4];
    const __half* pB[4];
    uint32_t soff[4];
#pragma unroll
    for (int v = 0; v < 4; v++) {
        int r = r0 + v * 32;
        soff[v] = (uint32_t)r * 128 + (uint32_t)((seg ^ (r & 7)) * 16);
        pA[v] = g_h_hi + (size_t)(m0 + r) * 1024 + seg * 8;
        pB[v] = g_w_hi + (size_t)(n0 + r) * 1024 + seg * 8;
    }

#define ISSUE_CHUNK(BUF) do {                                             \
    uint32_t sbase = sb + (BUF) * STAGE_STRIDE;                           \
    _Pragma("unroll")                                                     \
    for (int v = 0; v < 4; v++) {                                         \
        cp16(sbase + OFF_A + soff[v], pA[v]);                             \
        cp16(sbase + OFF_B + soff[v], pB[v]);                             \
        pA[v] += 64; pB[v] += 64;                                         \
    }                                                                     \
    asm volatile("cp.async.commit_group;" ::: "memory");                  \
} while (0)

    const int lrow  = lane & 15;
    const int lhalf = lane >> 4;

    // Hoisted swizzle bases: offset(ks) = rX + (((ks*2+lhalf)<<4) ^ r7X)
    int rA[2], r7A[2], rB[4], r7B[4];
#pragma unroll
    for (int mi = 0; mi < 2; mi++) {
        int r = wm * 32 + mi * 16 + lrow;
        rA[mi] = r * 128; r7A[mi] = (r & 7) * 16;
    }
#pragma unroll
    for (int ng = 0; ng < 4; ng++) {
        int r = wn * 64 + ng * 16 + lrow;
        rB[ng] = r * 128; r7B[ng] = (r & 7) * 16;
    }

    float acc[2][8][4] = {};

    // prologue: stages 0 and 1
    ISSUE_CHUNK(0);
    ISSUE_CHUNK(1);

    int buf = 0;
    for (int c = 0; c < 16; c++) {
        if (c < 15) asm volatile("cp.async.wait_group 1;" ::: "memory");
        else        asm volatile("cp.async.wait_group 0;" ::: "memory");
        __syncthreads();          // all warps done with buf (c+2)%3's old data
        if (c < 14) {
            int nb = buf + 2; if (nb >= 3) nb -= 3;
            ISSUE_CHUNK(nb);
        }
        const uint32_t st = sb + buf * STAGE_STRIDE;

#pragma unroll
        for (int ks = 0; ks < 4; ks++) {
            uint32_t kk = (uint32_t)((ks * 2 + lhalf) * 16);
            uint32_t aF[2][4];
            uint32_t bF[4][4];
#pragma unroll
            for (int mi = 0; mi < 2; mi++) {
                uint32_t off = (uint32_t)rA[mi] + (kk ^ (uint32_t)r7A[mi]);
                LDSM4(aF[mi], st + OFF_A + off);
            }
#pragma unroll
            for (int ng = 0; ng < 4; ng++) {
                uint32_t off = (uint32_t)rB[ng] + (kk ^ (uint32_t)r7B[ng]);
                LDSM4(bF[ng], st + OFF_B + off);
            }
#pragma unroll
            for (int mi = 0; mi < 2; mi++)
#pragma unroll
                for (int nt = 0; nt < 8; nt++) {
                    int ng = nt >> 1, hf = nt & 1;
                    mma16816h(acc[mi][nt], aF[mi], bF[ng][hf], bF[ng][2 + hf]);
                }
        }
        if (++buf >= 3) buf = 0;
    }

    // Epilogue: tanh(acc + bias) dot v_w, reduced over this warp's 64 cols.
    const int g = lane >> 2, tig = lane & 3;
#pragma unroll
    for (int mi = 0; mi < 2; mi++)
#pragma unroll
        for (int rg = 0; rg < 2; rg++) {
            float s = 0.f;
#pragma unroll
            for (int nt = 0; nt < 8; nt++) {
                int col = wn * 64 + nt * 8 + tig * 2;
                float p0 = acc[mi][nt][rg * 2 + 0] + sbias[col];
                float p1 = acc[mi][nt][rg * 2 + 1] + sbias[col + 1];
                s = fmaf(tanh_fast(p0), svw[col], s);
                s = fmaf(tanh_fast(p1), svw[col + 1], s);
            }
            s += __shfl_down_sync(0xffffffffu, s, 1, 4);
            s += __shfl_down_sync(0xffffffffu, s, 2, 4);
            if (tig == 0) {
                int row = m0 + wm * 32 + mi * 16 + rg * 8 + g;
                g_spart[(size_t)(blockIdx.x * 2 + wn) * BL + row] = s;
            }
        }
}

// ------------------------------- small kernels -----------------------------
__global__ void convert_h_kernel(const float* __restrict__ h) {
    size_t i = ((size_t)blockIdx.x * 256 + threadIdx.x) * 8;
    float4 v0 = *reinterpret_cast<const float4*>(h + i);
    float4 v1 = *reinterpret_cast<const float4*>(h + i + 4);
    union { __half2 p[4]; uint4 u; } out;
    out.p[0] = __floats2half2_rn(v0.x, v0.y);
    out.p[1] = __floats2half2_rn(v0.z, v0.w);
    out.p[2] = __floats2half2_rn(v1.x, v1.y);
    out.p[3] = __floats2half2_rn(v1.z, v1.w);
    *reinterpret_cast<uint4*>(g_h_hi + i) = out.u;
}

__global__ void convert_w_kernel(const float* __restrict__ ln_w) {
    size_t e = ((size_t)blockIdx.x * 256 + threadIdx.x) * 4;
    int n = (int)(e >> 10), k = (int)(e & 1023);
    float4 v = *reinterpret_cast<const float4*>(ln_w + (size_t)n * 2048 + k);
    union { __half2 p[2]; uint64_t u; } out;
    out.p[0] = __floats2half2_rn(v.x, v.y);
    out.p[1] = __floats2half2_rn(v.z, v.w);
    *reinterpret_cast<uint64_t*>(g_w_hi + e) = out.u;
}

__global__ void bias_kernel(const float* __restrict__ ln_w,
                            const float* __restrict__ ln_b,
                            const float* __restrict__ vq) {
    int hh = blockIdx.x;
    const float* wrow = ln_w + (size_t)hh * 2048 + 1024;
    float sum = 0.f;
    for (int i = threadIdx.x; i < 1024; i += 256)
        sum = fmaf(wrow[i], vq[i], sum);
    __shared__ float red[256];
    red[threadIdx.x] = sum;
    __syncthreads();
    for (int st = 128; st > 0; st >>= 1) {
        if (threadIdx.x < st) red[threadIdx.x] += red[threadIdx.x + st];
        __syncthreads();
    }
    if (threadIdx.x == 0) g_bias[hh] = ln_b[hh] + red[0];
}

__global__ void softmax_kernel(const int* __restrict__ mask) {
    int b = blockIdx.x;
    __shared__ float red[256];
    float vals[8];
    float mx = -1e30f;
#pragma unroll
    for (int j = 0; j < 8; j++) {
        int idx = b * LLEN + threadIdx.x + j * 256;
        float v = 0.f;
#pragma unroll
        for (int ct = 0; ct < NCTS; ct++)
            v += g_spart[(size_t)ct * BL + idx];
        if (mask[idx] == 0) v -= 10000.f;
        vals[j] = v;
        mx = fmaxf(mx, v);
    }
    red[threadIdx.x] = mx;
    __syncthreads();
    for (int st = 128; st > 0; st >>= 1) {
        if (threadIdx.x < st) red[threadIdx.x] = fmaxf(red[threadIdx.x], red[threadIdx.x + st]);
        __syncthreads();
    }
    mx = red[0];
    __syncthreads();
    float se = 0.f;
#pragma unroll
    for (int j = 0; j < 8; j++) { vals[j] = __expf(vals[j] - mx); se += vals[j]; }
    red[threadIdx.x] = se;
    __syncthreads();
    for (int st = 128; st > 0; st >>= 1) {
        if (threadIdx.x < st) red[threadIdx.x] += red[threadIdx.x + st];
        __syncthreads();
    }
    float inv = 1.f / red[0];
#pragma unroll
    for (int j = 0; j < 8; j++)
        g_a[b * LLEN + threadIdx.x + j * 256] = vals[j] * inv;
}

// wsum split over 8 L-slices for occupancy; deterministic fixed partition.
__global__ void __launch_bounds__(256)
wsum_part_kernel(const float* __restrict__ h) {
    int b = blockIdx.y, sl = blockIdx.z;
    int c = blockIdx.x * 256 + threadIdx.x;
    int l0 = sl * 256;
    __shared__ float aw[256];
    aw[threadIdx.x] = g_a[b * LLEN + l0 + threadIdx.x];
    __syncthreads();
    const float* hp = h + ((size_t)b * LLEN + l0) * 1024 + c;
    float acc = 0.f;
#pragma unroll 8
    for (int l = 0; l < 256; l++)
        acc = fmaf(aw[l], hp[(size_t)l * 1024], acc);
    g_rpart[sl][b * 1024 + c] = acc;
}

__global__ void wsum_reduce_kernel(float* __restrict__ out) {
    int i = blockIdx.x * 256 + threadIdx.x;
    float acc = 0.f;
#pragma unroll
    for (int sl = 0; sl < 8; sl++) acc += g_rpart[sl][i];
    out[i] = acc;
}

// ---------------------------------------------------------------------------
extern "C" void kernel_launch(void* const* d_in, const int* in_sizes, int n_in,
                              void* d_out, int out_size) {
    const float* h    = (const float*)d_in[0];
    const int*   mask = (const int*)d_in[1];
    const float* ln_w = (const float*)d_in[2];
    const float* ln_b = (const float*)d_in[3];
    const float* v_w  = (const float*)d_in[4];
    const float* vq   = (const float*)d_in[5];
    float* out = (float*)d_out;

    cudaFuncSetAttribute(gemm_mma_kernel,
                         cudaFuncAttributeMaxDynamicSharedMemorySize, SMEM_BYTES);

    convert_h_kernel<<<32768, 256>>>(h);
    convert_w_kernel<<<1024, 256>>>(ln_w);
    bias_kernel<<<1024, 256>>>(ln_w, ln_b, vq);

    gemm_mma_kernel<<<dim3(8, 512), 256, SMEM_BYTES>>>(v_w);

    softmax_kernel<<<BATCH, 256>>>(mask);

    wsum_part_kernel<<<dim3(4, BATCH, 8), 256>>>(h);
    wsum_reduce_kernel<<<128, 256>>>(out);
}

// round 9
// speedup vs baseline: 8.2047x; 1.0409x over previous
#include <cuda_runtime.h>
#include <cuda_fp16.h>
#include <cstdint>

#define BATCH 32
#define LLEN  2048
#define BL    (BATCH * LLEN)      // 65536
#define NCTS  16                  // 16 partial s arrays (8 ntiles x 2 warp halves)

// ------------------------------- device scratch ----------------------------
__device__ __align__(16) __half g_h_hi[67108864];   // [BL][1024] fp16(h)
__device__ __align__(16) __half g_w_hi[1048576];    // [1024 N][1024 K] fp16(W)
__device__ float g_bias[1024];
__device__ float g_spart[NCTS * BL];
__device__ float g_a[BL];
__device__ float g_rpart[8][BATCH * 1024];

// ------------------------------- PTX helpers -------------------------------
__device__ __forceinline__ uint32_t smem_u32(const void* p) {
    uint32_t a;
    asm("{ .reg .u64 t; cvta.to.shared.u64 t, %1; cvt.u32.u64 %0, t; }" : "=r"(a) : "l"(p));
    return a;
}
__device__ __forceinline__ void cp16(uint32_t dst, const void* src) {
    asm volatile("cp.async.cg.shared.global [%0], [%1], 16;" :: "r"(dst), "l"(src));
}
#define LDSM4(r, addr) \
    asm volatile("ldmatrix.sync.aligned.m8n8.x4.shared.b16 {%0,%1,%2,%3}, [%4];" \
        : "=r"((r)[0]), "=r"((r)[1]), "=r"((r)[2]), "=r"((r)[3]) : "r"(addr))

__device__ __forceinline__ void mma16816h(float* d, const uint32_t* a,
                                          uint32_t b0, uint32_t b1) {
    asm volatile("mma.sync.aligned.m16n8k16.row.col.f32.f16.f16.f32 "
        "{%0,%1,%2,%3}, {%4,%5,%6,%7}, {%8,%9}, {%0,%1,%2,%3};"
        : "+f"(d[0]), "+f"(d[1]), "+f"(d[2]), "+f"(d[3])
        : "r"(a[0]), "r"(a[1]), "r"(a[2]), "r"(a[3]), "r"(b0), "r"(b1));
}

__device__ __forceinline__ float tanh_fast(float x) {
    float e = __expf(2.f * x);
    return 1.f - 2.f / (e + 1.f);
}

// ------------------------------- GEMM constants ----------------------------
// Per stage (32 KB): A 16K | B 16K (128 rows x 128 B, SW128). 3 stages = 96 KB
// + 1 KB params -> 2 CTAs/SM.
#define STAGE_STRIDE 32768
#define OFF_A 0
#define OFF_B 16384
#define OFF_SBIAS 98304
#define OFF_SVW   98816
#define SMEM_BYTES 99328

// ---------------------------------------------------------------------------
// HMMA GEMM: pre[128 rows, 128 cols] over K=1024, single-term fp16
// (fp16(h) x fp16(W), fp32 accumulate). 3-stage pipeline with early producer
// issue (sync -> issue -> wait), 2 CTAs/SM.
// grid (8 ntiles, 512 mtiles), 256 threads (8 warps: 4 M x 2 N).
// ---------------------------------------------------------------------------
__global__ void __launch_bounds__(256, 2)
gemm_mma_kernel(const float* __restrict__ v_w) {
    extern __shared__ char smem[];
    const uint32_t sb = smem_u32(smem);
    const int tid  = threadIdx.x;
    const int lane = tid & 31;
    const int warp = tid >> 5;
    const int wm   = warp & 3;        // 0..3: 32-row slice
    const int wn   = warp >> 2;       // 0..1: 64-col slice
    const int m0 = blockIdx.y * 128;
    const int n0 = blockIdx.x * 128;

    float* sbias = (float*)(smem + OFF_SBIAS);
    float* svw   = (float*)(smem + OFF_SVW);
    if (tid < 128) {
        sbias[tid] = g_bias[n0 + tid];
        svw[tid]   = v_w[n0 + tid];
    }

    // Producer state: hoisted pointers, advanced +64 halves per chunk.
    const int seg = tid & 7;
    const int r0  = tid >> 3;
    const __half* pA[4];
    const __half* pB[4];
    uint32_t soff[4];
#pragma unroll
    for (int v = 0; v < 4; v++) {
        int r = r0 + v * 32;
        soff[v] = (uint32_t)r * 128 + (uint32_t)((seg ^ (r & 7)) * 16);
        pA[v] = g_h_hi + (size_t)(m0 + r) * 1024 + seg * 8;
        pB[v] = g_w_hi + (size_t)(n0 + r) * 1024 + seg * 8;
    }

#define ISSUE_CHUNK(BUF) do {                                             \
    uint32_t sbase = sb + (BUF) * STAGE_STRIDE;                           \
    _Pragma("unroll")                                                     \
    for (int v = 0; v < 4; v++) {                                         \
        cp16(sbase + OFF_A + soff[v], pA[v]);                             \
        cp16(sbase + OFF_B + soff[v], pB[v]);                             \
        pA[v] += 64; pB[v] += 64;                                         \
    }                                                                     \
    asm volatile("cp.async.commit_group;" ::: "memory");                  \
} while (0)

    const int lrow  = lane & 15;
    const int lhalf = lane >> 4;

    // Hoisted swizzle bases: offset(ks) = rX + (((ks*2+lhalf)<<4) ^ r7X)
    int rA[2], r7A[2], rB[4], r7B[4];
#pragma unroll
    for (int mi = 0; mi < 2; mi++) {
        int r = wm * 32 + mi * 16 + lrow;
        rA[mi] = r * 128; r7A[mi] = (r & 7) * 16;
    }
#pragma unroll
    for (int ng = 0; ng < 4; ng++) {
        int r = wn * 64 + ng * 16 + lrow;
        rB[ng] = r * 128; r7B[ng] = (r & 7) * 16;
    }

    float acc[2][8][4] = {};

    // prologue: stages 0 and 1
    ISSUE_CHUNK(0);
    ISSUE_CHUNK(1);

    int buf = 0;
    for (int c = 0; c < 16; c++) {
        __syncthreads();          // all warps done with buf (c+2)%3's old data
        if (c < 14) {
            int nb = buf + 2; if (nb >= 3) nb -= 3;
            ISSUE_CHUNK(nb);      // enqueue next chunk BEFORE blocking
            asm volatile("cp.async.wait_group 2;" ::: "memory");   // chunk c done
        } else if (c == 14) {
            asm volatile("cp.async.wait_group 1;" ::: "memory");
        } else {
            asm volatile("cp.async.wait_group 0;" ::: "memory");
        }
        __syncthreads();          // chunk c visible to all warps
        const uint32_t st = sb + buf * STAGE_STRIDE;

#pragma unroll
        for (int ks = 0; ks < 4; ks++) {
            uint32_t kk = (uint32_t)((ks * 2 + lhalf) * 16);
            uint32_t aF[2][4];
            uint32_t bF[4][4];
#pragma unroll
            for (int mi = 0; mi < 2; mi++) {
                uint32_t off = (uint32_t)rA[mi] + (kk ^ (uint32_t)r7A[mi]);
                LDSM4(aF[mi], st + OFF_A + off);
            }
#pragma unroll
            for (int ng = 0; ng < 4; ng++) {
                uint32_t off = (uint32_t)rB[ng] + (kk ^ (uint32_t)r7B[ng]);
                LDSM4(bF[ng], st + OFF_B + off);
            }
#pragma unroll
            for (int mi = 0; mi < 2; mi++)
#pragma unroll
                for (int nt = 0; nt < 8; nt++) {
                    int ng = nt >> 1, hf = nt & 1;
                    mma16816h(acc[mi][nt], aF[mi], bF[ng][hf], bF[ng][2 + hf]);
                }
        }
        if (++buf >= 3) buf = 0;
    }

    // Epilogue: tanh(acc + bias) dot v_w, reduced over this warp's 64 cols.
    const int g = lane >> 2, tig = lane & 3;
#pragma unroll
    for (int mi = 0; mi < 2; mi++)
#pragma unroll
        for (int rg = 0; rg < 2; rg++) {
            float s = 0.f;
#pragma unroll
            for (int nt = 0; nt < 8; nt++) {
                int col = wn * 64 + nt * 8 + tig * 2;
                float p0 = acc[mi][nt][rg * 2 + 0] + sbias[col];
                float p1 = acc[mi][nt][rg * 2 + 1] + sbias[col + 1];
                s = fmaf(tanh_fast(p0), svw[col], s);
                s = fmaf(tanh_fast(p1), svw[col + 1], s);
            }
            s += __shfl_down_sync(0xffffffffu, s, 1, 4);
            s += __shfl_down_sync(0xffffffffu, s, 2, 4);
            if (tig == 0) {
                int row = m0 + wm * 32 + mi * 16 + rg * 8 + g;
                g_spart[(size_t)(blockIdx.x * 2 + wn) * BL + row] = s;
            }
        }
}

// ------------------------------- small kernels -----------------------------
__global__ void convert_h_kernel(const float* __restrict__ h) {
    size_t i = ((size_t)blockIdx.x * 256 + threadIdx.x) * 8;
    float4 v0 = *reinterpret_cast<const float4*>(h + i);
    float4 v1 = *reinterpret_cast<const float4*>(h + i + 4);
    union { __half2 p[4]; uint4 u; } out;
    out.p[0] = __floats2half2_rn(v0.x, v0.y);
    out.p[1] = __floats2half2_rn(v0.z, v0.w);
    out.p[2] = __floats2half2_rn(v1.x, v1.y);
    out.p[3] = __floats2half2_rn(v1.z, v1.w);
    *reinterpret_cast<uint4*>(g_h_hi + i) = out.u;
}

__global__ void convert_w_kernel(const float* __restrict__ ln_w) {
    size_t e = ((size_t)blockIdx.x * 256 + threadIdx.x) * 4;
    int n = (int)(e >> 10), k = (int)(e & 1023);
    float4 v = *reinterpret_cast<const float4*>(ln_w + (size_t)n * 2048 + k);
    union { __half2 p[2]; uint64_t u; } out;
    out.p[0] = __floats2half2_rn(v.x, v.y);
    out.p[1] = __floats2half2_rn(v.z, v.w);
    *reinterpret_cast<uint64_t*>(g_w_hi + e) = out.u;
}

__global__ void bias_kernel(const float* __restrict__ ln_w,
                            const float* __restrict__ ln_b,
                            const float* __restrict__ vq) {
    int hh = blockIdx.x;
    const float* wrow = ln_w + (size_t)hh * 2048 + 1024;
    float sum = 0.f;
    for (int i = threadIdx.x; i < 1024; i += 256)
        sum = fmaf(wrow[i], vq[i], sum);
    __shared__ float red[256];
    red[threadIdx.x] = sum;
    __syncthreads();
    for (int st = 128; st > 0; st >>= 1) {
        if (threadIdx.x < st) red[threadIdx.x] += red[threadIdx.x + st];
        __syncthreads();
    }
    if (threadIdx.x == 0) g_bias[hh] = ln_b[hh] + red[0];
}

__global__ void softmax_kernel(const int* __restrict__ mask) {
    int b = blockIdx.x;
    __shared__ float red[256];
    float vals[8];
    float mx = -1e30f;
#pragma unroll
    for (int j = 0; j < 8; j++) {
        int idx = b * LLEN + threadIdx.x + j * 256;
        float v = 0.f;
#pragma unroll
        for (int ct = 0; ct < NCTS; ct++)
            v += g_spart[(size_t)ct * BL + idx];
        if (mask[idx] == 0) v -= 10000.f;
        vals[j] = v;
        mx = fmaxf(mx, v);
    }
    red[threadIdx.x] = mx;
    __syncthreads();
    for (int st = 128; st > 0; st >>= 1) {
        if (threadIdx.x < st) red[threadIdx.x] = fmaxf(red[threadIdx.x], red[threadIdx.x + st]);
        __syncthreads();
    }
    mx = red[0];
    __syncthreads();
    float se = 0.f;
#pragma unroll
    for (int j = 0; j < 8; j++) { vals[j] = __expf(vals[j] - mx); se += vals[j]; }
    red[threadIdx.x] = se;
    __syncthreads();
    for (int st = 128; st > 0; st >>= 1) {
        if (threadIdx.x < st) red[threadIdx.x] += red[threadIdx.x + st];
        __syncthreads();
    }
    float inv = 1.f / red[0];
#pragma unroll
    for (int j = 0; j < 8; j++)
        g_a[b * LLEN + threadIdx.x + j * 256] = vals[j] * inv;
}

// wsum over fp16 h (reuses g_h_hi): r[b,c] = sum_l a[b,l] * h[b,l,c].
// Each thread owns 2 adjacent columns (half2); 8 L-slices; fp32 accumulate.
// grid (1024cols/512, 32, 8), 256 threads.
__global__ void __launch_bounds__(256)
wsum_part_kernel() {
    int b = blockIdx.y, sl = blockIdx.z;
    int c2 = blockIdx.x * 256 + threadIdx.x;       // half2 column index
    int l0 = sl * 256;
    __shared__ float aw[256];
    aw[threadIdx.x] = g_a[b * LLEN + l0 + threadIdx.x];
    __syncthreads();
    const __half2* hp = reinterpret_cast<const __half2*>(g_h_hi) +
                        ((size_t)b * LLEN + l0) * 512 + c2;
    float accx = 0.f, accy = 0.f;
#pragma unroll 8
    for (int l = 0; l < 256; l++) {
        float2 v = __half22float2(hp[(size_t)l * 512]);
        float w = aw[l];
        accx = fmaf(w, v.x, accx);
        accy = fmaf(w, v.y, accy);
    }
    float2* dst = reinterpret_cast<float2*>(&g_rpart[sl][b * 1024 + c2 * 2]);
    *dst = make_float2(accx, accy);
}

__global__ void wsum_reduce_kernel(float* __restrict__ out) {
    int i = blockIdx.x * 256 + threadIdx.x;
    float acc = 0.f;
#pragma unroll
    for (int sl = 0; sl < 8; sl++) acc += g_rpart[sl][i];
    out[i] = acc;
}

// ---------------------------------------------------------------------------
extern "C" void kernel_launch(void* const* d_in, const int* in_sizes, int n_in,
                              void* d_out, int out_size) {
    const float* h    = (const float*)d_in[0];
    const int*   mask = (const int*)d_in[1];
    const float* ln_w = (const float*)d_in[2];
    const float* ln_b = (const float*)d_in[3];
    const float* v_w  = (const float*)d_in[4];
    const float* vq   = (const float*)d_in[5];
    float* out = (float*)d_out;

    cudaFuncSetAttribute(gemm_mma_kernel,
                         cudaFuncAttributeMaxDynamicSharedMemorySize, SMEM_BYTES);

    convert_h_kernel<<<32768, 256>>>(h);
    convert_w_kernel<<<1024, 256>>>(ln_w);
    bias_kernel<<<1024, 256>>>(ln_w, ln_b, vq);

    gemm_mma_kernel<<<dim3(8, 512), 256, SMEM_BYTES>>>(v_w);

    softmax_kernel<<<BATCH, 256>>>(mask);

    wsum_part_kernel<<<dim3(2, BATCH, 8), 256>>>();
    wsum_reduce_kernel<<<128, 256>>>(out);
}